// round 14
// baseline (speedup 1.0000x reference)
#include <cuda_runtime.h>

#define HID  2048
#define NE   64
#define NK   8
#define BT   64    // tokens per block
#define KC   32    // K staging chunk
#define NTHR 256
#define XP   4
#define WP   4
#define LP   1

typedef unsigned long long u64;

__device__ int g_counts[NE];

__device__ __forceinline__ u64 pk2(float a, float b) {
    u64 r; asm("mov.b64 %0, {%1, %2};" : "=l"(r) : "f"(a), "f"(b)); return r;
}
__device__ __forceinline__ void upk2(u64 v, float& a, float& b) {
    asm("mov.b64 {%0, %1}, %2;" : "=f"(a), "=f"(b) : "l"(v));
}
__device__ __forceinline__ u64 ffma2(u64 a, u64 b, u64 c) {
    u64 d; asm("fma.rn.f32x2 %0, %1, %2, %3;" : "=l"(d) : "l"(a), "l"(b), "l"(c)); return d;
}
__device__ __forceinline__ u64 fadd2(u64 a, u64 b) {
    u64 d; asm("add.rn.f32x2 %0, %1, %2;" : "=l"(d) : "l"(a), "l"(b)); return d;
}
__device__ __forceinline__ u64 fmul2(u64 a, u64 b) {
    u64 d; asm("mul.rn.f32x2 %0, %1, %2;" : "=l"(d) : "l"(a), "l"(b)); return d;
}

struct GemmSm {
    float x[KC][BT + XP];   // transposed: [k][token]
    float w[KC][NE + WP];   // transposed: [k][expert]
};

__global__ __launch_bounds__(NTHR) void router_kernel(
    const float* __restrict__ x, const float* __restrict__ gw,
    const float* __restrict__ bias, const float* __restrict__ noise,
    float* __restrict__ outW, float* __restrict__ outI, float* __restrict__ outP)
{
    __shared__ union { GemmSm g; float l[BT][NE + LP]; } sm;
    __shared__ float bias_s[NE];
    __shared__ int   hist_s[NE];

    const int tid = threadIdx.x;
    const int t0  = blockIdx.x * BT;

    if (tid < NE) { bias_s[tid] = bias[tid]; hist_s[tid] = 0; }

    const int tg = tid >> 3;   // token pair 0..31 (2 tokens each)
    const int eg = tid & 7;    // expert group 0..7 (8 experts each)

    // 3-level accumulation: cacc (8 k) -> mid (64 k) -> acc (master)
    u64 acc[2][4], mid[2][4];
    #pragma unroll
    for (int i = 0; i < 2; i++)
        #pragma unroll
        for (int p = 0; p < 4; p++) { acc[i][p] = pk2(0.f, 0.f); mid[i][p] = pk2(0.f, 0.f); }

    const float4* x4 = (const float4*)(x + (size_t)t0 * HID);
    const float4* w4 = (const float4*)gw;

    for (int k0 = 0; k0 < HID; k0 += KC) {
        __syncthreads();
        // ---- stage x tile transposed: 64 tokens x 32 k (512 float4, 2/thread) ----
        #pragma unroll
        for (int c = 0; c < 2; c++) {
            int f = c * NTHR + tid;
            int row = f >> 3, col4 = f & 7;
            float4 v = x4[(size_t)row * (HID / 4) + (k0 >> 2) + col4];
            sm.g.x[col4 * 4 + 0][row] = v.x;
            sm.g.x[col4 * 4 + 1][row] = v.y;
            sm.g.x[col4 * 4 + 2][row] = v.z;
            sm.g.x[col4 * 4 + 3][row] = v.w;
        }
        // ---- stage w tile transposed: 64 experts x 32 k (512 float4, 2/thread) ----
        #pragma unroll
        for (int c = 0; c < 2; c++) {
            int f = c * NTHR + tid;
            int e = f >> 3, col4 = f & 7;
            float4 v = w4[(size_t)e * (HID / 4) + (k0 >> 2) + col4];
            sm.g.w[col4 * 4 + 0][e] = v.x;
            sm.g.w[col4 * 4 + 1][e] = v.y;
            sm.g.w[col4 * 4 + 2][e] = v.z;
            sm.g.w[col4 * 4 + 3][e] = v.w;
        }
        __syncthreads();

        const bool firstm = ((k0 >> 5) & 1) == 0;   // mid spans 2 KC tiles (64 k)

        #pragma unroll
        for (int sub = 0; sub < 4; sub++) {
            u64 cacc[2][4];
            #pragma unroll
            for (int kk = 0; kk < 8; kk++) {
                const int kc = sub * 8 + kk;
                const float2     xv = *(const float2*)&sm.g.x[kc][tg * 2];
                const ulonglong2 wA = *(const ulonglong2*)&sm.g.w[kc][eg * 8];
                const ulonglong2 wB = *(const ulonglong2*)&sm.g.w[kc][eg * 8 + 4];
                u64 xx;
                xx = pk2(xv.x, xv.x);
                if (kk == 0) {
                    cacc[0][0] = fmul2(xx, wA.x); cacc[0][1] = fmul2(xx, wA.y);
                    cacc[0][2] = fmul2(xx, wB.x); cacc[0][3] = fmul2(xx, wB.y);
                } else {
                    cacc[0][0] = ffma2(xx, wA.x, cacc[0][0]); cacc[0][1] = ffma2(xx, wA.y, cacc[0][1]);
                    cacc[0][2] = ffma2(xx, wB.x, cacc[0][2]); cacc[0][3] = ffma2(xx, wB.y, cacc[0][3]);
                }
                xx = pk2(xv.y, xv.y);
                if (kk == 0) {
                    cacc[1][0] = fmul2(xx, wA.x); cacc[1][1] = fmul2(xx, wA.y);
                    cacc[1][2] = fmul2(xx, wB.x); cacc[1][3] = fmul2(xx, wB.y);
                } else {
                    cacc[1][0] = ffma2(xx, wA.x, cacc[1][0]); cacc[1][1] = ffma2(xx, wA.y, cacc[1][1]);
                    cacc[1][2] = ffma2(xx, wB.x, cacc[1][2]); cacc[1][3] = ffma2(xx, wB.y, cacc[1][3]);
                }
            }
            // merge chunk into mid
            if (sub == 0 && firstm) {
                #pragma unroll
                for (int i = 0; i < 2; i++)
                    #pragma unroll
                    for (int p = 0; p < 4; p++) mid[i][p] = cacc[i][p];
            } else {
                #pragma unroll
                for (int i = 0; i < 2; i++)
                    #pragma unroll
                    for (int p = 0; p < 4; p++) mid[i][p] = fadd2(mid[i][p], cacc[i][p]);
            }
        }
        if (!firstm) {
            #pragma unroll
            for (int i = 0; i < 2; i++)
                #pragma unroll
                for (int p = 0; p < 4; p++) acc[i][p] = fadd2(acc[i][p], mid[i][p]);
        }
    }

    // ---- dump logits into smem (reuse union) ----
    __syncthreads();
    #pragma unroll
    for (int i = 0; i < 2; i++) {
        int t = tg * 2 + i;
        #pragma unroll
        for (int p = 0; p < 4; p++) {
            float a, b; upk2(acc[i][p], a, b);
            sm.l[t][eg * 8 + 2 * p]     = a;
            sm.l[t][eg * 8 + 2 * p + 1] = b;
        }
    }
    __syncthreads();

    // ---- per-token epilogue: noise+bias, softmax, probs, top-8, hist ----
    if (tid < BT) {
        const int gt = t0 + tid;
        const float4* nrow = (const float4*)(noise + (size_t)gt * NE);

        float maxv = -3.402823466e38f;
        #pragma unroll
        for (int e = 0; e < NE; e += 4) {
            float4 nz = nrow[e >> 2];
            float v0 = sm.l[tid][e + 0] + nz.x * 0.01f + bias_s[e + 0];
            float v1 = sm.l[tid][e + 1] + nz.y * 0.01f + bias_s[e + 1];
            float v2 = sm.l[tid][e + 2] + nz.z * 0.01f + bias_s[e + 2];
            float v3 = sm.l[tid][e + 3] + nz.w * 0.01f + bias_s[e + 3];
            sm.l[tid][e + 0] = v0; sm.l[tid][e + 1] = v1;
            sm.l[tid][e + 2] = v2; sm.l[tid][e + 3] = v3;
            maxv = fmaxf(maxv, fmaxf(fmaxf(v0, v1), fmaxf(v2, v3)));
        }
        float sum = 0.f;
        #pragma unroll
        for (int e = 0; e < NE; e++) {
            float p = expf(sm.l[tid][e] - maxv);
            sm.l[tid][e] = p;
            sum += p;
        }
        float* prow = outP + (size_t)gt * NE;
        #pragma unroll
        for (int e = 0; e < NE; e += 4) {
            float4 v;
            v.x = sm.l[tid][e + 0] / sum; v.y = sm.l[tid][e + 1] / sum;
            v.z = sm.l[tid][e + 2] / sum; v.w = sm.l[tid][e + 3] / sum;
            sm.l[tid][e + 0] = v.x; sm.l[tid][e + 1] = v.y;
            sm.l[tid][e + 2] = v.z; sm.l[tid][e + 3] = v.w;
            *(float4*)(prow + e) = v;
        }
        // top-8, stable: strictly-greater ascending scan => lowest index on ties
        u64 taken = 0ull;
        float wv[NK]; int wi[NK]; float wsum = 0.f;
        #pragma unroll
        for (int k = 0; k < NK; k++) {
            float bv = -1.f; int bi = 0;
            for (int e = 0; e < NE; e++) {
                float p = sm.l[tid][e];
                if (!((taken >> e) & 1ull) && p > bv) { bv = p; bi = e; }
            }
            taken |= 1ull << bi;
            wv[k] = bv; wi[k] = bi; wsum += bv;
        }
        #pragma unroll
        for (int k = 0; k < NK; k++) {
            outW[(size_t)gt * NK + k] = wv[k] / wsum;
            outI[(size_t)gt * NK + k] = (float)wi[k];
            atomicAdd(&hist_s[wi[k]], 1);
        }
    }
    __syncthreads();
    if (tid < NE) atomicAdd(&g_counts[tid], hist_s[tid]);
}

__global__ void zero_counts_kernel() { g_counts[threadIdx.x] = 0; }

__global__ void finalize_bias_kernel(const float* __restrict__ bias,
                                     float* __restrict__ outB, int target) {
    int e = threadIdx.x;
    int c = g_counts[e];
    float s = (c > target) ? 1.f : ((c < target) ? -1.f : 0.f);
    outB[e] = bias[e] - 0.001f * s;
}

extern "C" void kernel_launch(void* const* d_in, const int* in_sizes, int n_in,
                              void* d_out, int out_size) {
    const float* x     = (const float*)d_in[0];
    const float* gw    = (const float*)d_in[1];
    const float* bias  = (const float*)d_in[2];
    const float* noise = (const float*)d_in[3];
    const int T = in_sizes[0] / HID;   // 32768

    float* out  = (float*)d_out;
    float* outW = out;                            // [T, 8]
    float* outI = out + (size_t)T * NK;           // [T, 8] indices as float
    float* outP = out + (size_t)T * NK * 2;       // [T, 64]
    float* outB = outP + (size_t)T * NE;          // [64]

    zero_counts_kernel<<<1, NE>>>();
    router_kernel<<<T / BT, NTHR>>>(x, gw, bias, noise, outW, outI, outP);
    finalize_bias_kernel<<<1, NE>>>(bias, outB, T * NK / NE);
}